// round 12
// baseline (speedup 1.0000x reference)
#include <cuda_runtime.h>

#define NEGV (-1000000000.0f)

// B=2 S=2048 D=1024 H=16 A=64
// Fragment-major tf32-bit buffers:
__device__ unsigned g_q[(size_t)4096 * 1024];     // A-frag per (b,h,qt,mt,kt)
__device__ unsigned g_k[(size_t)4096 * 1024];     // B-frag (n=key,k=dim)
__device__ unsigned g_v[(size_t)4096 * 1024];     // B-frag (n=dim,k=key)
__device__ unsigned g_ctx[(size_t)4096 * 1024];   // A-frag (gemm2 A)
__device__ unsigned g_qsT[(size_t)4096 * 1024];   // A-frag (gemm1 A)
__device__ unsigned g_wqkvT[(size_t)1024 * 3072]; // B-frag (gemm1 B)
__device__ unsigned g_woutT[(size_t)1024 * 1024]; // B-frag (gemm2 B)

__device__ __forceinline__ unsigned f2tf32(float x) {
    unsigned y;
    asm("cvt.rna.tf32.f32 %0, %1;" : "=r"(y) : "f"(x));
    return y;
}

__device__ __forceinline__ void mma_tf32(float* d, const unsigned* a, const unsigned* b) {
    asm volatile(
        "mma.sync.aligned.m16n8k8.row.col.f32.tf32.tf32.f32 "
        "{%0,%1,%2,%3}, {%4,%5,%6,%7}, {%8,%9}, {%0,%1,%2,%3};"
        : "+f"(d[0]), "+f"(d[1]), "+f"(d[2]), "+f"(d[3])
        : "r"(a[0]), "r"(a[1]), "r"(a[2]), "r"(a[3]), "r"(b[0]), "r"(b[1]));
}

__device__ __forceinline__ unsigned sptr(const void* p) {
    return (unsigned)__cvta_generic_to_shared(p);
}

__device__ __forceinline__ void cpa16(unsigned s, const void* g) {
    asm volatile("cp.async.cg.shared.global [%0], [%1], 16;\n" :: "r"(s), "l"(g));
}

// ---------------------------------------------------------------------------
// Input permutation kernels (round-8 proven)
// ---------------------------------------------------------------------------
__global__ __launch_bounds__(256) void permA_tf32(
    const float4* __restrict__ src, unsigned* __restrict__ dst,
    int C, int total4)
{
    int idx = blockIdx.x * 256 + threadIdx.x;
    if (idx >= total4) return;
    const int C4 = C >> 2;
    const int r = idx / C4;
    const int k = (idx - r * C4) * 4;
    float4 v = src[idx];
    const int Ct = C >> 3;
    const int mt = r >> 4, rm = r & 15;
    const int gp = rm & 7, im = rm >> 3;
    const int kt = k >> 3, ik = (k & 7) >> 2;
    unsigned* tb = dst + ((size_t)mt * Ct + kt) * 128 + ik * 2 + im;
    tb[(gp * 4 + 0) * 4] = f2tf32(v.x);
    tb[(gp * 4 + 1) * 4] = f2tf32(v.y);
    tb[(gp * 4 + 2) * 4] = f2tf32(v.z);
    tb[(gp * 4 + 3) * 4] = f2tf32(v.w);
}

__global__ __launch_bounds__(256) void permB_tf32(
    const float4* __restrict__ src, unsigned* __restrict__ dst,
    int N, int total4)
{
    int idx = blockIdx.x * 256 + threadIdx.x;
    if (idx >= total4) return;
    const int N4 = N >> 2;
    const int k = idx / N4;
    const int n = (idx - k * N4) * 4;
    float4 v = src[idx];
    const int Nt = N >> 3;
    const int kt = k >> 3, tg = k & 3, ik = (k & 7) >> 2;
    const int nt = n >> 3, g0 = n & 7;
    unsigned* tb = dst + ((size_t)kt * Nt + nt) * 64 + tg * 2 + ik;
    tb[(g0 + 0) * 8] = f2tf32(v.x);
    tb[(g0 + 1) * 8] = f2tf32(v.y);
    tb[(g0 + 2) * 8] = f2tf32(v.z);
    tb[(g0 + 3) * 8] = f2tf32(v.w);
}

// ---------------------------------------------------------------------------
// TF32 SGEMM (round-11 proven: 512 threads, 16 warps 4x4, 32x32 warp tile,
// 3-stage cp.async ring). mode 0: fp32 C + bias. mode 1: scatter to Q/K/V.
// ---------------------------------------------------------------------------
#define STG_W 4096

__global__ __launch_bounds__(512, 2) void sgemm_tf32(
    const unsigned* __restrict__ A, const unsigned* __restrict__ B,
    const float* __restrict__ bias, void* __restrict__ Cout,
    unsigned* __restrict__ qbuf, unsigned* __restrict__ kbuf,
    unsigned* __restrict__ vbuf,
    int M, int N, int K, int mode)
{
    extern __shared__ unsigned smg[];
    unsigned* As = smg;                 // [3][4096]
    unsigned* Bs = smg + 3 * STG_W;     // [3][4096]

    const int tid = threadIdx.x;
    const int bx = blockIdx.x, by = blockIdx.y;
    const int lane = tid & 31, wid = tid >> 5;
    const int g = lane >> 2, tig = lane & 3;
    const int wm = (wid & 3) * 32;
    const int wn = (wid >> 2) * 32;
    const int Ct = K >> 3;
    const int Nt = N >> 3;

    const int amt = tid >> 6;
    const int aq  = (tid & 63) * 8;
    const int bkt = tid >> 7;
    const int bq  = (tid & 127) * 8;

    const unsigned* abase = A + ((size_t)(by * 8 + amt) * Ct) * 128 + aq;
    const unsigned* bbase = B + (size_t)bx * 16 * 64 + bq;

    const unsigned sa_base = sptr(&As[amt * 512 + aq]);
    const unsigned sb_base = sptr(&Bs[bkt * 1024 + bq]);

    float acc[2][4][4];
#pragma unroll
    for (int mt = 0; mt < 2; mt++)
#pragma unroll
        for (int nt = 0; nt < 4; nt++)
#pragma unroll
            for (int i = 0; i < 4; i++) acc[mt][nt][i] = 0.0f;

    const int nt_iters = K >> 5;

#pragma unroll
    for (int p = 0; p < 2; p++) {
        const unsigned* ag = abase + p * 4 * 128;
        const unsigned* bg = bbase + (size_t)(p * 4 + bkt) * Nt * 64;
        const unsigned sa = sa_base + p * (STG_W * 4);
        const unsigned sb = sb_base + p * (STG_W * 4);
#pragma unroll
        for (int i = 0; i < 2; i++) cpa16(sa + i * 16, ag + i * 4);
#pragma unroll
        for (int i = 0; i < 2; i++) cpa16(sb + i * 16, bg + i * 4);
        asm volatile("cp.async.commit_group;\n");
    }

    for (int t = 0; t < nt_iters; t++) {
        if (t + 1 < nt_iters)
            asm volatile("cp.async.wait_group 1;\n");
        else
            asm volatile("cp.async.wait_group 0;\n");
        __syncthreads();

        if (t + 2 < nt_iters) {
            const int s = (t + 2) % 3;
            const unsigned* ag = abase + (t + 2) * 4 * 128;
            const unsigned* bg = bbase + (size_t)((t + 2) * 4 + bkt) * Nt * 64;
            const unsigned sa = sa_base + s * (STG_W * 4);
            const unsigned sb = sb_base + s * (STG_W * 4);
#pragma unroll
            for (int i = 0; i < 2; i++) cpa16(sa + i * 16, ag + i * 4);
#pragma unroll
            for (int i = 0; i < 2; i++) cpa16(sb + i * 16, bg + i * 4);
        }
        asm volatile("cp.async.commit_group;\n");

        const unsigned* Ab = As + (t % 3) * STG_W;
        const unsigned* Bb = Bs + (t % 3) * STG_W;

#pragma unroll
        for (int ks = 0; ks < 4; ks++) {
            uint4 af[2];
            uint2 bf[4];
#pragma unroll
            for (int mt = 0; mt < 2; mt++)
                af[mt] = *(const uint4*)&Ab[(((wid & 3) * 2 + mt) * 4 + ks) * 128 + lane * 4];
#pragma unroll
            for (int nt = 0; nt < 4; nt++)
                bf[nt] = *(const uint2*)&Bb[(ks * 16 + (wid >> 2) * 4 + nt) * 64 + lane * 2];
#pragma unroll
            for (int mt = 0; mt < 2; mt++)
#pragma unroll
                for (int nt = 0; nt < 4; nt++)
                    mma_tf32(acc[mt][nt], (const unsigned*)&af[mt], (const unsigned*)&bf[nt]);
        }
    }

    if (mode == 1) {
#pragma unroll
        for (int mt = 0; mt < 2; mt++) {
            const int row = by * 128 + wm + mt * 16 + g;
            const int bb = row >> 11;
            const int s = row & 2047;
#pragma unroll
            for (int nt = 0; nt < 4; nt++) {
                const int col = bx * 128 + wn + nt * 8 + 2 * tig;
                unsigned v00 = f2tf32(acc[mt][nt][0]);
                unsigned v01 = f2tf32(acc[mt][nt][1]);
                unsigned v10 = f2tf32(acc[mt][nt][2]);
                unsigned v11 = f2tf32(acc[mt][nt][3]);
                if (col < 1024) {            // Q -> A-frag
                    const int h = col >> 6, d = col & 63;
                    const int bh = bb * 16 + h;
                    size_t base = (((size_t)(bh * 16 + (s >> 7)) * 8 + ((s & 127) >> 4)) * 8
                                   + (d >> 3)) * 128;
                    const int gq = s & 7;
                    const int w0 = (gq * 4 + (d & 3)) * 4 + ((d & 7) >> 2) * 2;
                    const int d1 = d + 1;
                    const int w1 = (gq * 4 + (d1 & 3)) * 4 + ((d1 & 7) >> 2) * 2;
                    uint2 u0; u0.x = v00; u0.y = v10;
                    uint2 u1; u1.x = v01; u1.y = v11;
                    *(uint2*)&qbuf[base + w0] = u0;
                    *(uint2*)&qbuf[base + w1] = u1;
                } else if (col < 2048) {     // K -> B-frag (n=key, k=dim)
                    const int h = (col - 1024) >> 6, d = (col - 1024) & 63;
                    const int bh = bb * 16 + h;
                    const int tt = s >> 6, key = s & 63;
                    unsigned* blk = kbuf + ((size_t)(bh * 32 + tt)) * 4096;
                    const int gk = key & 7;
                    const int tile0 = (d >> 3) * 8 + (key >> 3);
                    const int tile1 = (d >> 3) * 8 + ((key + 8) >> 3);
                    const int wd0 = (gk * 4 + (d & 3)) * 2 + ((d & 7) >> 2);
                    const int d1 = d + 1;
                    const int wd1 = (gk * 4 + (d1 & 3)) * 2 + ((d1 & 7) >> 2);
                    blk[tile0 * 64 + wd0] = v00;
                    blk[tile0 * 64 + wd1] = v01;
                    blk[tile1 * 64 + wd0] = v10;
                    blk[tile1 * 64 + wd1] = v11;
                } else {                     // V -> B-frag (n=dim, k=key)
                    const int h = (col - 2048) >> 6, d = (col - 2048) & 63;
                    const int bh = bb * 16 + h;
                    const int tt = s >> 6, key = s & 63;
                    unsigned* blk = vbuf + ((size_t)(bh * 32 + tt)) * 4096;
                    const int tigv = key & 3, ikv = (key & 7) >> 2;
                    const int tile0 = (key >> 3) * 8 + (d >> 3);
                    const int tile1 = ((key + 8) >> 3) * 8 + (d >> 3);
                    const int wv0 = ((d & 7) * 4 + tigv) * 2 + ikv;
                    const int d1 = d + 1;
                    const int wv1 = (((d1) & 7) * 4 + tigv) * 2 + ikv;
                    blk[tile0 * 64 + wv0] = v00;
                    blk[tile0 * 64 + wv1] = v01;
                    blk[tile1 * 64 + wv0] = v10;
                    blk[tile1 * 64 + wv1] = v11;
                }
            }
        }
    } else {
        float* C = (float*)Cout;
        float bv0[4], bv1[4];
#pragma unroll
        for (int nt = 0; nt < 4; nt++) {
            int col = bx * 128 + wn + nt * 8 + 2 * tig;
            bv0[nt] = bias ? bias[col] : 0.0f;
            bv1[nt] = bias ? bias[col + 1] : 0.0f;
        }
#pragma unroll
        for (int mt = 0; mt < 2; mt++) {
            int row = by * 128 + wm + mt * 16 + g;
#pragma unroll
            for (int nt = 0; nt < 4; nt++) {
                int col = bx * 128 + wn + nt * 8 + 2 * tig;
                float2 s0, s1;
                s0.x = acc[mt][nt][0] + bv0[nt];
                s0.y = acc[mt][nt][1] + bv1[nt];
                s1.x = acc[mt][nt][2] + bv0[nt];
                s1.y = acc[mt][nt][3] + bv1[nt];
                *(float2*)(C + (size_t)row * N + col) = s0;
                *(float2*)(C + (size_t)(row + 8) * N + col) = s1;
            }
        }
    }
}

// ---------------------------------------------------------------------------
// Fragment-major flash attention, round 12:
//  - 3 CTAs/SM target: smem 98.8 -> 68.5 KB (P staged one k-tile at a time:
//    s[ks] in C-frag layout IS A-frag k-tile ks), regs <= 85 (Q fragments
//    reloaded per (tile, ks) from L1 instead of hoisted).
//  - per-accumulator mma order unchanged -> bit-identical result.
// ---------------------------------------------------------------------------
#define KVW 4096

__global__ __launch_bounds__(256, 3) void attn_tc(
    const unsigned* __restrict__ qbuf, const unsigned* __restrict__ kbuf,
    const unsigned* __restrict__ vbuf, const int* __restrict__ mask,
    unsigned* __restrict__ ctx)
{
    extern __shared__ unsigned sm[];
    unsigned* Ksm = sm;                       // [2][4096]
    unsigned* Vsm = sm + 2 * KVW;             // [2][4096]
    unsigned* Pw  = sm + 4 * KVW;             // [8 warps][128]
    int*      Mk  = (int*)(sm + 4 * KVW + 1024);  // [2][64]

    const int tid = threadIdx.x;
    const int lane = tid & 31, wid = tid >> 5;
    const int g = lane >> 2, tig = lane & 3;

    const int qt = blockIdx.x;
    const int h  = blockIdx.y;
    const int b  = blockIdx.z;
    const int bh = b * 16 + h;

    const unsigned* qbase = qbuf + (((size_t)(bh * 16 + qt) * 8 + wid) * 8) * 128;

    const int off = tid * 16;
    const unsigned sk_base = sptr(&Ksm[off]);
    const unsigned sv_base = sptr(&Vsm[off]);
    const unsigned* kblk0 = kbuf + ((size_t)bh * 32) * KVW;
    const unsigned* vblk0 = vbuf + ((size_t)bh * 32) * KVW;

    {
#pragma unroll
        for (int i = 0; i < 4; i++) cpa16(sk_base + i * 16, kblk0 + off + i * 4);
#pragma unroll
        for (int i = 0; i < 4; i++) cpa16(sv_base + i * 16, vblk0 + off + i * 4);
        if (tid < 16) cpa16(sptr(&Mk[tid * 4]), mask + b * 2048 + tid * 4);
        asm volatile("cp.async.commit_group;\n");
    }

    float O[8][4];
#pragma unroll
    for (int nt = 0; nt < 8; nt++)
#pragma unroll
        for (int i = 0; i < 4; i++) O[nt][i] = 0.0f;
    float mA = -1e30f, mB = -1e30f, lA = 0.0f, lB = 0.0f;

    unsigned* Pme = Pw + wid * 128;

    for (int t = 0; t < 32; t++) {
        asm volatile("cp.async.wait_group 0;\n");
        __syncthreads();

        if (t + 1 < 32) {
            const int s = (t + 1) & 1;
            const unsigned* kg = kblk0 + (size_t)(t + 1) * KVW + off;
            const unsigned* vg = vblk0 + (size_t)(t + 1) * KVW + off;
            const unsigned sk = sk_base + s * (KVW * 4);
            const unsigned sv = sv_base + s * (KVW * 4);
#pragma unroll
            for (int i = 0; i < 4; i++) cpa16(sk + i * 16, kg + i * 4);
#pragma unroll
            for (int i = 0; i < 4; i++) cpa16(sv + i * 16, vg + i * 4);
            if (tid < 16) cpa16(sptr(&Mk[s * 64 + tid * 4]),
                                mask + b * 2048 + (t + 1) * 64 + tid * 4);
            asm volatile("cp.async.commit_group;\n");
        }

        const unsigned* Kb = Ksm + (t & 1) * KVW;
        const unsigned* Vb = Vsm + (t & 1) * KVW;
        const int*      Mb = Mk + (t & 1) * 64;

        // ---- S = Q K^T : qa reloaded per ks (L1-resident), nt inner ----
        float s[8][4];
#pragma unroll
        for (int nt = 0; nt < 8; nt++)
#pragma unroll
            for (int i = 0; i < 4; i++) s[nt][i] = 0.0f;

#pragma unroll
        for (int ks = 0; ks < 8; ks++) {
            const uint4 qa = *(const uint4*)&qbase[ks * 128 + lane * 4];
#pragma unroll
            for (int nt = 0; nt < 8; nt++) {
                uint2 bf = *(const uint2*)&Kb[(ks * 8 + nt) * 64 + lane * 2];
                mma_tf32(s[nt], (const unsigned*)&qa, (const unsigned*)&bf);
            }
        }

        // ---- mask + online softmax ----
        float mxA = -1e30f, mxB = -1e30f;
#pragma unroll
        for (int nt = 0; nt < 8; nt++) {
            const int c = nt * 8 + 2 * tig;
            const int m0 = Mb[c], m1 = Mb[c + 1];
            s[nt][0] = (m0 == 0) ? NEGV : s[nt][0] * 0.125f;
            s[nt][1] = (m1 == 0) ? NEGV : s[nt][1] * 0.125f;
            s[nt][2] = (m0 == 0) ? NEGV : s[nt][2] * 0.125f;
            s[nt][3] = (m1 == 0) ? NEGV : s[nt][3] * 0.125f;
            mxA = fmaxf(mxA, fmaxf(s[nt][0], s[nt][1]));
            mxB = fmaxf(mxB, fmaxf(s[nt][2], s[nt][3]));
        }
        mxA = fmaxf(mxA, __shfl_xor_sync(0xffffffffu, mxA, 1));
        mxA = fmaxf(mxA, __shfl_xor_sync(0xffffffffu, mxA, 2));
        mxB = fmaxf(mxB, __shfl_xor_sync(0xffffffffu, mxB, 1));
        mxB = fmaxf(mxB, __shfl_xor_sync(0xffffffffu, mxB, 2));

        const float mnA = fmaxf(mA, mxA);
        const float mnB = fmaxf(mB, mxB);
        const float alphaA = __expf(mA - mnA);
        const float alphaB = __expf(mB - mnB);
        float sumA = 0.0f, sumB = 0.0f;
#pragma unroll
        for (int nt = 0; nt < 8; nt++) {
            s[nt][0] = __expf(s[nt][0] - mnA);
            s[nt][1] = __expf(s[nt][1] - mnA);
            s[nt][2] = __expf(s[nt][2] - mnB);
            s[nt][3] = __expf(s[nt][3] - mnB);
            sumA += s[nt][0] + s[nt][1];
            sumB += s[nt][2] + s[nt][3];
        }
        sumA += __shfl_xor_sync(0xffffffffu, sumA, 1);
        sumA += __shfl_xor_sync(0xffffffffu, sumA, 2);
        sumB += __shfl_xor_sync(0xffffffffu, sumB, 1);
        sumB += __shfl_xor_sync(0xffffffffu, sumB, 2);
        lA = lA * alphaA + sumA;  mA = mnA;
        lB = lB * alphaB + sumB;  mB = mnB;
#pragma unroll
        for (int nt = 0; nt < 8; nt++) {
            O[nt][0] *= alphaA; O[nt][1] *= alphaA;
            O[nt][2] *= alphaB; O[nt][3] *= alphaB;
        }

        // ---- O += P V : stage one A-frag k-tile of P at a time ----
#pragma unroll
        for (int ks = 0; ks < 8; ks++) {
            const int d0 = 2 * tig, d1 = 2 * tig + 1;
            const int w0 = (g * 4 + (d0 & 3)) * 4 + ((d0 & 7) >> 2) * 2;
            const int w1 = (g * 4 + (d1 & 3)) * 4 + ((d1 & 7) >> 2) * 2;
            uint2 u0; u0.x = f2tf32(s[ks][0]); u0.y = f2tf32(s[ks][2]);
            uint2 u1; u1.x = f2tf32(s[ks][1]); u1.y = f2tf32(s[ks][3]);
            *(uint2*)&Pme[w0] = u0;
            *(uint2*)&Pme[w1] = u1;
            __syncwarp();
            const uint4 pa = *(const uint4*)&Pme[lane * 4];
#pragma unroll
            for (int nt = 0; nt < 8; nt++) {
                uint2 bf = *(const uint2*)&Vb[(ks * 8 + nt) * 64 + lane * 2];
                mma_tf32(O[nt], (const unsigned*)&pa, (const unsigned*)&bf);
            }
            __syncwarp();  // pa consumed before next ks overwrites Pme
        }
    }

    // epilogue: ctx in A-frag tile layout (Ct = 128) for gemm2
    const float invA = 1.0f / lA;
    const float invB = 1.0f / lB;
    const int mt = (b * 2048 + qt * 128 + wid * 16) >> 4;
#pragma unroll
    for (int nt = 0; nt < 8; nt++) {
        const int kt = h * 8 + nt;
        unsigned* tb = ctx + ((size_t)mt * 128 + kt) * 128;
        const int tig2 = 2 * tig;
        const int ik = tig2 >> 2, tp = tig2 & 3;
        uint2 w0, w1;
        w0.x = f2tf32(O[nt][0] * invA);
        w0.y = f2tf32(O[nt][2] * invB);
        w1.x = f2tf32(O[nt][1] * invA);
        w1.y = f2tf32(O[nt][3] * invB);
        *(uint2*)&tb[(g * 4 + tp) * 4 + ik * 2]     = w0;
        *(uint2*)&tb[(g * 4 + tp + 1) * 4 + ik * 2] = w1;
    }
}

// ---------------------------------------------------------------------------
extern "C" void kernel_launch(void* const* d_in, const int* in_sizes, int n_in,
                              void* d_out, int out_size)
{
    const float* qs   = (const float*)d_in[0];
    const int*   mask = (const int*)d_in[1];
    const float* Wqkv = (const float*)d_in[2];
    const float* Wout = (const float*)d_in[3];
    const float* bout = (const float*)d_in[4];
    float* out = (float*)d_out;

    unsigned *qP, *kP, *vP, *ctxP, *qsT, *wqkvT, *woutT;
    cudaGetSymbolAddress((void**)&qP,    g_q);
    cudaGetSymbolAddress((void**)&kP,    g_k);
    cudaGetSymbolAddress((void**)&vP,    g_v);
    cudaGetSymbolAddress((void**)&ctxP,  g_ctx);
    cudaGetSymbolAddress((void**)&qsT,   g_qsT);
    cudaGetSymbolAddress((void**)&wqkvT, g_wqkvT);
    cudaGetSymbolAddress((void**)&woutT, g_woutT);

    const int gemmSmem = 6 * STG_W * 4;  // 98304 B
    cudaFuncSetAttribute(sgemm_tf32,
                         cudaFuncAttributeMaxDynamicSharedMemorySize, gemmSmem);

    const int attnSmem = (4 * KVW + 1024 + 128) * 4;  // 70144 B
    cudaFuncSetAttribute(attn_tc,
                         cudaFuncAttributeMaxDynamicSharedMemorySize, attnSmem);

    // 0) pre-convert + permute inputs into fragment-major tf32 layouts
    permA_tf32<<<4096, 256>>>((const float4*)qs, qsT, 1024, 4096 * 1024 / 4);
    permB_tf32<<<3072, 256>>>((const float4*)Wqkv, wqkvT, 3072, 1024 * 3072 / 4);
    permB_tf32<<<1024, 256>>>((const float4*)Wout, woutT, 1024, 1024 * 1024 / 4);

    // 1) qkv = qs @ Wqkv, scattered into fragment-major Q/K/V buffers
    sgemm_tf32<<<dim3(24, 32), 512, gemmSmem>>>(
        qsT, wqkvT, nullptr, nullptr, qP, kP, vP, 4096, 3072, 1024, 1);

    // 2) fused masked attention -> ctx (A-frag layout)
    attn_tc<<<dim3(16, 16, 2), 256, attnSmem>>>(qP, kP, vP, mask, ctxP);

    // 3) out = ctx @ Wout + bout  (fp32 final)
    sgemm_tf32<<<dim3(8, 32), 512, gemmSmem>>>(
        ctxP, woutT, bout, out, nullptr, nullptr, nullptr, 4096, 1024, 1024, 0);
}

// round 13
// speedup vs baseline: 1.0898x; 1.0898x over previous
#include <cuda_runtime.h>

#define NEGV (-1000000000.0f)

// B=2 S=2048 D=1024 H=16 A=64
// Fragment-major tf32-bit buffers:
__device__ unsigned g_q[(size_t)4096 * 1024];     // A-frag per (b,h,qt,mt,kt)
__device__ unsigned g_k[(size_t)4096 * 1024];     // B-frag (n=key,k=dim)
__device__ unsigned g_v[(size_t)4096 * 1024];     // B-frag (n=dim,k=key)
__device__ unsigned g_ctx[(size_t)4096 * 1024];   // A-frag (gemm2 A)
__device__ unsigned g_qsT[(size_t)4096 * 1024];   // A-frag (gemm1 A)
__device__ unsigned g_wqkvT[(size_t)1024 * 3072]; // B-frag (gemm1 B)
__device__ unsigned g_woutT[(size_t)1024 * 1024]; // B-frag (gemm2 B)

__device__ __forceinline__ unsigned f2tf32(float x) {
    unsigned y;
    asm("cvt.rna.tf32.f32 %0, %1;" : "=r"(y) : "f"(x));
    return y;
}

__device__ __forceinline__ void mma_tf32(float* d, const unsigned* a, const unsigned* b) {
    asm volatile(
        "mma.sync.aligned.m16n8k8.row.col.f32.tf32.tf32.f32 "
        "{%0,%1,%2,%3}, {%4,%5,%6,%7}, {%8,%9}, {%0,%1,%2,%3};"
        : "+f"(d[0]), "+f"(d[1]), "+f"(d[2]), "+f"(d[3])
        : "r"(a[0]), "r"(a[1]), "r"(a[2]), "r"(a[3]), "r"(b[0]), "r"(b[1]));
}

__device__ __forceinline__ unsigned sptr(const void* p) {
    return (unsigned)__cvta_generic_to_shared(p);
}

__device__ __forceinline__ void cpa16(unsigned s, const void* g) {
    asm volatile("cp.async.cg.shared.global [%0], [%1], 16;\n" :: "r"(s), "l"(g));
}

// ---------------------------------------------------------------------------
// Input permutation kernels (round-8 proven)
// ---------------------------------------------------------------------------
__global__ __launch_bounds__(256) void permA_tf32(
    const float4* __restrict__ src, unsigned* __restrict__ dst,
    int C, int total4)
{
    int idx = blockIdx.x * 256 + threadIdx.x;
    if (idx >= total4) return;
    const int C4 = C >> 2;
    const int r = idx / C4;
    const int k = (idx - r * C4) * 4;
    float4 v = src[idx];
    const int Ct = C >> 3;
    const int mt = r >> 4, rm = r & 15;
    const int gp = rm & 7, im = rm >> 3;
    const int kt = k >> 3, ik = (k & 7) >> 2;
    unsigned* tb = dst + ((size_t)mt * Ct + kt) * 128 + ik * 2 + im;
    tb[(gp * 4 + 0) * 4] = f2tf32(v.x);
    tb[(gp * 4 + 1) * 4] = f2tf32(v.y);
    tb[(gp * 4 + 2) * 4] = f2tf32(v.z);
    tb[(gp * 4 + 3) * 4] = f2tf32(v.w);
}

__global__ __launch_bounds__(256) void permB_tf32(
    const float4* __restrict__ src, unsigned* __restrict__ dst,
    int N, int total4)
{
    int idx = blockIdx.x * 256 + threadIdx.x;
    if (idx >= total4) return;
    const int N4 = N >> 2;
    const int k = idx / N4;
    const int n = (idx - k * N4) * 4;
    float4 v = src[idx];
    const int Nt = N >> 3;
    const int kt = k >> 3, tg = k & 3, ik = (k & 7) >> 2;
    const int nt = n >> 3, g0 = n & 7;
    unsigned* tb = dst + ((size_t)kt * Nt + nt) * 64 + tg * 2 + ik;
    tb[(g0 + 0) * 8] = f2tf32(v.x);
    tb[(g0 + 1) * 8] = f2tf32(v.y);
    tb[(g0 + 2) * 8] = f2tf32(v.z);
    tb[(g0 + 3) * 8] = f2tf32(v.w);
}

// ---------------------------------------------------------------------------
// TF32 SGEMM (round-11 proven: 512 threads, 16 warps 4x4, 32x32 warp tile,
// 3-stage cp.async ring). mode 0: fp32 C + bias. mode 1: scatter to Q/K/V.
// ---------------------------------------------------------------------------
#define STG_W 4096

__global__ __launch_bounds__(512, 2) void sgemm_tf32(
    const unsigned* __restrict__ A, const unsigned* __restrict__ B,
    const float* __restrict__ bias, void* __restrict__ Cout,
    unsigned* __restrict__ qbuf, unsigned* __restrict__ kbuf,
    unsigned* __restrict__ vbuf,
    int M, int N, int K, int mode)
{
    extern __shared__ unsigned smg[];
    unsigned* As = smg;                 // [3][4096]
    unsigned* Bs = smg + 3 * STG_W;     // [3][4096]

    const int tid = threadIdx.x;
    const int bx = blockIdx.x, by = blockIdx.y;
    const int lane = tid & 31, wid = tid >> 5;
    const int g = lane >> 2, tig = lane & 3;
    const int wm = (wid & 3) * 32;
    const int wn = (wid >> 2) * 32;
    const int Ct = K >> 3;
    const int Nt = N >> 3;

    const int amt = tid >> 6;
    const int aq  = (tid & 63) * 8;
    const int bkt = tid >> 7;
    const int bq  = (tid & 127) * 8;

    const unsigned* abase = A + ((size_t)(by * 8 + amt) * Ct) * 128 + aq;
    const unsigned* bbase = B + (size_t)bx * 16 * 64 + bq;

    const unsigned sa_base = sptr(&As[amt * 512 + aq]);
    const unsigned sb_base = sptr(&Bs[bkt * 1024 + bq]);

    float acc[2][4][4];
#pragma unroll
    for (int mt = 0; mt < 2; mt++)
#pragma unroll
        for (int nt = 0; nt < 4; nt++)
#pragma unroll
            for (int i = 0; i < 4; i++) acc[mt][nt][i] = 0.0f;

    const int nt_iters = K >> 5;

#pragma unroll
    for (int p = 0; p < 2; p++) {
        const unsigned* ag = abase + p * 4 * 128;
        const unsigned* bg = bbase + (size_t)(p * 4 + bkt) * Nt * 64;
        const unsigned sa = sa_base + p * (STG_W * 4);
        const unsigned sb = sb_base + p * (STG_W * 4);
#pragma unroll
        for (int i = 0; i < 2; i++) cpa16(sa + i * 16, ag + i * 4);
#pragma unroll
        for (int i = 0; i < 2; i++) cpa16(sb + i * 16, bg + i * 4);
        asm volatile("cp.async.commit_group;\n");
    }

    for (int t = 0; t < nt_iters; t++) {
        if (t + 1 < nt_iters)
            asm volatile("cp.async.wait_group 1;\n");
        else
            asm volatile("cp.async.wait_group 0;\n");
        __syncthreads();

        if (t + 2 < nt_iters) {
            const int s = (t + 2) % 3;
            const unsigned* ag = abase + (t + 2) * 4 * 128;
            const unsigned* bg = bbase + (size_t)((t + 2) * 4 + bkt) * Nt * 64;
            const unsigned sa = sa_base + s * (STG_W * 4);
            const unsigned sb = sb_base + s * (STG_W * 4);
#pragma unroll
            for (int i = 0; i < 2; i++) cpa16(sa + i * 16, ag + i * 4);
#pragma unroll
            for (int i = 0; i < 2; i++) cpa16(sb + i * 16, bg + i * 4);
        }
        asm volatile("cp.async.commit_group;\n");

        const unsigned* Ab = As + (t % 3) * STG_W;
        const unsigned* Bb = Bs + (t % 3) * STG_W;

#pragma unroll
        for (int ks = 0; ks < 4; ks++) {
            uint4 af[2];
            uint2 bf[4];
#pragma unroll
            for (int mt = 0; mt < 2; mt++)
                af[mt] = *(const uint4*)&Ab[(((wid & 3) * 2 + mt) * 4 + ks) * 128 + lane * 4];
#pragma unroll
            for (int nt = 0; nt < 4; nt++)
                bf[nt] = *(const uint2*)&Bb[(ks * 16 + (wid >> 2) * 4 + nt) * 64 + lane * 2];
#pragma unroll
            for (int mt = 0; mt < 2; mt++)
#pragma unroll
                for (int nt = 0; nt < 4; nt++)
                    mma_tf32(acc[mt][nt], (const unsigned*)&af[mt], (const unsigned*)&bf[nt]);
        }
    }

    if (mode == 1) {
#pragma unroll
        for (int mt = 0; mt < 2; mt++) {
            const int row = by * 128 + wm + mt * 16 + g;
            const int bb = row >> 11;
            const int s = row & 2047;
#pragma unroll
            for (int nt = 0; nt < 4; nt++) {
                const int col = bx * 128 + wn + nt * 8 + 2 * tig;
                unsigned v00 = f2tf32(acc[mt][nt][0]);
                unsigned v01 = f2tf32(acc[mt][nt][1]);
                unsigned v10 = f2tf32(acc[mt][nt][2]);
                unsigned v11 = f2tf32(acc[mt][nt][3]);
                if (col < 1024) {            // Q -> A-frag
                    const int h = col >> 6, d = col & 63;
                    const int bh = bb * 16 + h;
                    size_t base = (((size_t)(bh * 16 + (s >> 7)) * 8 + ((s & 127) >> 4)) * 8
                                   + (d >> 3)) * 128;
                    const int gq = s & 7;
                    const int w0 = (gq * 4 + (d & 3)) * 4 + ((d & 7) >> 2) * 2;
                    const int d1 = d + 1;
                    const int w1 = (gq * 4 + (d1 & 3)) * 4 + ((d1 & 7) >> 2) * 2;
                    uint2 u0; u0.x = v00; u0.y = v10;
                    uint2 u1; u1.x = v01; u1.y = v11;
                    *(uint2*)&qbuf[base + w0] = u0;
                    *(uint2*)&qbuf[base + w1] = u1;
                } else if (col < 2048) {     // K -> B-frag (n=key, k=dim)
                    const int h = (col - 1024) >> 6, d = (col - 1024) & 63;
                    const int bh = bb * 16 + h;
                    const int tt = s >> 6, key = s & 63;
                    unsigned* blk = kbuf + ((size_t)(bh * 32 + tt)) * 4096;
                    const int gk = key & 7;
                    const int tile0 = (d >> 3) * 8 + (key >> 3);
                    const int tile1 = (d >> 3) * 8 + ((key + 8) >> 3);
                    const int wd0 = (gk * 4 + (d & 3)) * 2 + ((d & 7) >> 2);
                    const int d1 = d + 1;
                    const int wd1 = (gk * 4 + (d1 & 3)) * 2 + ((d1 & 7) >> 2);
                    blk[tile0 * 64 + wd0] = v00;
                    blk[tile0 * 64 + wd1] = v01;
                    blk[tile1 * 64 + wd0] = v10;
                    blk[tile1 * 64 + wd1] = v11;
                } else {                     // V -> B-frag (n=dim, k=key)
                    const int h = (col - 2048) >> 6, d = (col - 2048) & 63;
                    const int bh = bb * 16 + h;
                    const int tt = s >> 6, key = s & 63;
                    unsigned* blk = vbuf + ((size_t)(bh * 32 + tt)) * 4096;
                    const int tigv = key & 3, ikv = (key & 7) >> 2;
                    const int tile0 = (key >> 3) * 8 + (d >> 3);
                    const int tile1 = ((key + 8) >> 3) * 8 + (d >> 3);
                    const int wv0 = ((d & 7) * 4 + tigv) * 2 + ikv;
                    const int d1 = d + 1;
                    const int wv1 = (((d1) & 7) * 4 + tigv) * 2 + ikv;
                    blk[tile0 * 64 + wv0] = v00;
                    blk[tile0 * 64 + wv1] = v01;
                    blk[tile1 * 64 + wv0] = v10;
                    blk[tile1 * 64 + wv1] = v11;
                }
            }
        }
    } else {
        float* C = (float*)Cout;
        float bv0[4], bv1[4];
#pragma unroll
        for (int nt = 0; nt < 4; nt++) {
            int col = bx * 128 + wn + nt * 8 + 2 * tig;
            bv0[nt] = bias ? bias[col] : 0.0f;
            bv1[nt] = bias ? bias[col + 1] : 0.0f;
        }
#pragma unroll
        for (int mt = 0; mt < 2; mt++) {
            int row = by * 128 + wm + mt * 16 + g;
#pragma unroll
            for (int nt = 0; nt < 4; nt++) {
                int col = bx * 128 + wn + nt * 8 + 2 * tig;
                float2 s0, s1;
                s0.x = acc[mt][nt][0] + bv0[nt];
                s0.y = acc[mt][nt][1] + bv1[nt];
                s1.x = acc[mt][nt][2] + bv0[nt];
                s1.y = acc[mt][nt][3] + bv1[nt];
                *(float2*)(C + (size_t)row * N + col) = s0;
                *(float2*)(C + (size_t)(row + 8) * N + col) = s1;
            }
        }
    }
}

// ---------------------------------------------------------------------------
// Fragment-major flash attention, round 13 = round-11 base (2 CTAs/SM,
// Q hoisted, full P buffer, one syncwarp/tile) with BOTH mma loops
// reordered ks-outer/nt-inner: 8 independent accumulator chains instead of
// 8-deep dependent chains. Per-accumulator ks order unchanged ->
// bit-identical result.
// ---------------------------------------------------------------------------
#define KVW 4096

__global__ __launch_bounds__(256, 2) void attn_tc(
    const unsigned* __restrict__ qbuf, const unsigned* __restrict__ kbuf,
    const unsigned* __restrict__ vbuf, const int* __restrict__ mask,
    unsigned* __restrict__ ctx)
{
    extern __shared__ unsigned sm[];
    unsigned* Ksm = sm;                       // [2][4096]
    unsigned* Vsm = sm + 2 * KVW;             // [2][4096]
    unsigned* Pw  = sm + 4 * KVW;             // [8 warps][1024]
    int*      Mk  = (int*)(sm + 4 * KVW + 8192);  // [2][64]

    const int tid = threadIdx.x;
    const int lane = tid & 31, wid = tid >> 5;
    const int g = lane >> 2, tig = lane & 3;

    const int qt = blockIdx.x;
    const int h  = blockIdx.y;
    const int b  = blockIdx.z;
    const int bh = b * 16 + h;

    const unsigned* qbase = qbuf + (((size_t)(bh * 16 + qt) * 8 + wid) * 8) * 128;
    uint4 qa[8];
#pragma unroll
    for (int ks = 0; ks < 8; ks++)
        qa[ks] = *(const uint4*)&qbase[ks * 128 + lane * 4];

    const int off = tid * 16;
    const unsigned sk_base = sptr(&Ksm[off]);
    const unsigned sv_base = sptr(&Vsm[off]);
    const unsigned* kblk0 = kbuf + ((size_t)bh * 32) * KVW;
    const unsigned* vblk0 = vbuf + ((size_t)bh * 32) * KVW;

    {
#pragma unroll
        for (int i = 0; i < 4; i++) cpa16(sk_base + i * 16, kblk0 + off + i * 4);
#pragma unroll
        for (int i = 0; i < 4; i++) cpa16(sv_base + i * 16, vblk0 + off + i * 4);
        if (tid < 16) cpa16(sptr(&Mk[tid * 4]), mask + b * 2048 + tid * 4);
        asm volatile("cp.async.commit_group;\n");
    }

    float O[8][4];
#pragma unroll
    for (int nt = 0; nt < 8; nt++)
#pragma unroll
        for (int i = 0; i < 4; i++) O[nt][i] = 0.0f;
    float mA = -1e30f, mB = -1e30f, lA = 0.0f, lB = 0.0f;

    unsigned* Pme = Pw + wid * 1024;

    for (int t = 0; t < 32; t++) {
        asm volatile("cp.async.wait_group 0;\n");
        __syncthreads();

        if (t + 1 < 32) {
            const int s = (t + 1) & 1;
            const unsigned* kg = kblk0 + (size_t)(t + 1) * KVW + off;
            const unsigned* vg = vblk0 + (size_t)(t + 1) * KVW + off;
            const unsigned sk = sk_base + s * (KVW * 4);
            const unsigned sv = sv_base + s * (KVW * 4);
#pragma unroll
            for (int i = 0; i < 4; i++) cpa16(sk + i * 16, kg + i * 4);
#pragma unroll
            for (int i = 0; i < 4; i++) cpa16(sv + i * 16, vg + i * 4);
            if (tid < 16) cpa16(sptr(&Mk[s * 64 + tid * 4]),
                                mask + b * 2048 + (t + 1) * 64 + tid * 4);
            asm volatile("cp.async.commit_group;\n");
        }

        const unsigned* Kb = Ksm + (t & 1) * KVW;
        const unsigned* Vb = Vsm + (t & 1) * KVW;
        const int*      Mb = Mk + (t & 1) * 64;

        // ---- S = Q K^T : ks-outer -> 8 independent accumulator chains ----
        float s[8][4];
#pragma unroll
        for (int nt = 0; nt < 8; nt++)
#pragma unroll
            for (int i = 0; i < 4; i++) s[nt][i] = 0.0f;

#pragma unroll
        for (int ks = 0; ks < 8; ks++) {
#pragma unroll
            for (int nt = 0; nt < 8; nt++) {
                uint2 bf = *(const uint2*)&Kb[(ks * 8 + nt) * 64 + lane * 2];
                mma_tf32(s[nt], (const unsigned*)&qa[ks], (const unsigned*)&bf);
            }
        }

        // ---- mask + online softmax ----
        float mxA = -1e30f, mxB = -1e30f;
#pragma unroll
        for (int nt = 0; nt < 8; nt++) {
            const int c = nt * 8 + 2 * tig;
            const int m0 = Mb[c], m1 = Mb[c + 1];
            s[nt][0] = (m0 == 0) ? NEGV : s[nt][0] * 0.125f;
            s[nt][1] = (m1 == 0) ? NEGV : s[nt][1] * 0.125f;
            s[nt][2] = (m0 == 0) ? NEGV : s[nt][2] * 0.125f;
            s[nt][3] = (m1 == 0) ? NEGV : s[nt][3] * 0.125f;
            mxA = fmaxf(mxA, fmaxf(s[nt][0], s[nt][1]));
            mxB = fmaxf(mxB, fmaxf(s[nt][2], s[nt][3]));
        }
        mxA = fmaxf(mxA, __shfl_xor_sync(0xffffffffu, mxA, 1));
        mxA = fmaxf(mxA, __shfl_xor_sync(0xffffffffu, mxA, 2));
        mxB = fmaxf(mxB, __shfl_xor_sync(0xffffffffu, mxB, 1));
        mxB = fmaxf(mxB, __shfl_xor_sync(0xffffffffu, mxB, 2));

        const float mnA = fmaxf(mA, mxA);
        const float mnB = fmaxf(mB, mxB);
        const float alphaA = __expf(mA - mnA);
        const float alphaB = __expf(mB - mnB);
        float sumA = 0.0f, sumB = 0.0f;
#pragma unroll
        for (int nt = 0; nt < 8; nt++) {
            s[nt][0] = __expf(s[nt][0] - mnA);
            s[nt][1] = __expf(s[nt][1] - mnA);
            s[nt][2] = __expf(s[nt][2] - mnB);
            s[nt][3] = __expf(s[nt][3] - mnB);
            sumA += s[nt][0] + s[nt][1];
            sumB += s[nt][2] + s[nt][3];
        }
        sumA += __shfl_xor_sync(0xffffffffu, sumA, 1);
        sumA += __shfl_xor_sync(0xffffffffu, sumA, 2);
        sumB += __shfl_xor_sync(0xffffffffu, sumB, 1);
        sumB += __shfl_xor_sync(0xffffffffu, sumB, 2);
        lA = lA * alphaA + sumA;  mA = mnA;
        lB = lB * alphaB + sumB;  mB = mnB;
#pragma unroll
        for (int nt = 0; nt < 8; nt++) {
            O[nt][0] *= alphaA; O[nt][1] *= alphaA;
            O[nt][2] *= alphaB; O[nt][3] *= alphaB;
        }

        // ---- P -> per-warp A-frag smem (all 8 k-tiles), one syncwarp ----
#pragma unroll
        for (int nt = 0; nt < 8; nt++) {
            const int d0 = 2 * tig, d1 = 2 * tig + 1;
            const int w0 = (g * 4 + (d0 & 3)) * 4 + ((d0 & 7) >> 2) * 2;
            const int w1 = (g * 4 + (d1 & 3)) * 4 + ((d1 & 7) >> 2) * 2;
            uint2 u0; u0.x = f2tf32(s[nt][0]); u0.y = f2tf32(s[nt][2]);
            uint2 u1; u1.x = f2tf32(s[nt][1]); u1.y = f2tf32(s[nt][3]);
            *(uint2*)&Pme[nt * 128 + w0] = u0;
            *(uint2*)&Pme[nt * 128 + w1] = u1;
        }
        __syncwarp();

        // ---- O += P V : ks-outer, one pa tile live, nt-inner independent ----
#pragma unroll
        for (int ks = 0; ks < 8; ks++) {
            const uint4 pa = *(const uint4*)&Pme[ks * 128 + lane * 4];
#pragma unroll
            for (int nt = 0; nt < 8; nt++) {
                uint2 bf = *(const uint2*)&Vb[(ks * 8 + nt) * 64 + lane * 2];
                mma_tf32(O[nt], (const unsigned*)&pa, (const unsigned*)&bf);
            }
        }
    }

    // epilogue: ctx in A-frag tile layout (Ct = 128) for gemm2
    const float invA = 1.0f / lA;
    const float invB = 1.0f / lB;
    const int mt = (b * 2048 + qt * 128 + wid * 16) >> 4;
#pragma unroll
    for (int nt = 0; nt < 8; nt++) {
        const int kt = h * 8 + nt;
        unsigned* tb = ctx + ((size_t)mt * 128 + kt) * 128;
        const int tig2 = 2 * tig;
        const int ik = tig2 >> 2, tp = tig2 & 3;
        uint2 w0, w1;
        w0.x = f2tf32(O[nt][0] * invA);
        w0.y = f2tf32(O[nt][2] * invB);
        w1.x = f2tf32(O[nt][1] * invA);
        w1.y = f2tf32(O[nt][3] * invB);
        *(uint2*)&tb[(g * 4 + tp) * 4 + ik * 2]     = w0;
        *(uint2*)&tb[(g * 4 + tp + 1) * 4 + ik * 2] = w1;
    }
}

// ---------------------------------------------------------------------------
extern "C" void kernel_launch(void* const* d_in, const int* in_sizes, int n_in,
                              void* d_out, int out_size)
{
    const float* qs   = (const float*)d_in[0];
    const int*   mask = (const int*)d_in[1];
    const float* Wqkv = (const float*)d_in[2];
    const float* Wout = (const float*)d_in[3];
    const float* bout = (const float*)d_in[4];
    float* out = (float*)d_out;

    unsigned *qP, *kP, *vP, *ctxP, *qsT, *wqkvT, *woutT;
    cudaGetSymbolAddress((void**)&qP,    g_q);
    cudaGetSymbolAddress((void**)&kP,    g_k);
    cudaGetSymbolAddress((void**)&vP,    g_v);
    cudaGetSymbolAddress((void**)&ctxP,  g_ctx);
    cudaGetSymbolAddress((void**)&qsT,   g_qsT);
    cudaGetSymbolAddress((void**)&wqkvT, g_wqkvT);
    cudaGetSymbolAddress((void**)&woutT, g_woutT);

    const int gemmSmem = 6 * STG_W * 4;  // 98304 B
    cudaFuncSetAttribute(sgemm_tf32,
                         cudaFuncAttributeMaxDynamicSharedMemorySize, gemmSmem);

    const int attnSmem = (4 * KVW + 8192 + 128) * 4;  // 98816 B
    cudaFuncSetAttribute(attn_tc,
                         cudaFuncAttributeMaxDynamicSharedMemorySize, attnSmem);

    // 0) pre-convert + permute inputs into fragment-major tf32 layouts
    permA_tf32<<<4096, 256>>>((const float4*)qs, qsT, 1024, 4096 * 1024 / 4);
    permB_tf32<<<3072, 256>>>((const float4*)Wqkv, wqkvT, 3072, 1024 * 3072 / 4);
    permB_tf32<<<1024, 256>>>((const float4*)Wout, woutT, 1024, 1024 * 1024 / 4);

    // 1) qkv = qs @ Wqkv, scattered into fragment-major Q/K/V buffers
    sgemm_tf32<<<dim3(24, 32), 512, gemmSmem>>>(
        qsT, wqkvT, nullptr, nullptr, qP, kP, vP, 4096, 3072, 1024, 1);

    // 2) fused masked attention -> ctx (A-frag layout)
    attn_tc<<<dim3(16, 16, 2), 256, attnSmem>>>(qP, kP, vP, mask, ctxP);

    // 3) out = ctx @ Wout + bout  (fp32 final)
    sgemm_tf32<<<dim3(8, 32), 512, gemmSmem>>>(
        ctxP, woutT, bout, out, nullptr, nullptr, nullptr, 4096, 1024, 1024, 0);
}

// round 14
// speedup vs baseline: 1.1115x; 1.0199x over previous
#include <cuda_runtime.h>

#define NEGV (-1000000000.0f)

// B=2 S=2048 D=1024 H=16 A=64
// Fragment-major tf32-bit buffers (B-frag layouts now PAIRED: two adjacent
// n-tiles interleaved so one LDS.128 per lane serves both).
__device__ unsigned g_q[(size_t)4096 * 1024];     // A-frag per (b,h,qt,mt,kt)
__device__ unsigned g_k[(size_t)4096 * 1024];     // paired B-frag (n=key,k=dim)
__device__ unsigned g_v[(size_t)4096 * 1024];     // paired B-frag (n=dim,k=key)
__device__ unsigned g_ctx[(size_t)4096 * 1024];   // A-frag (gemm2 A)
__device__ unsigned g_qsT[(size_t)4096 * 1024];   // A-frag (gemm1 A)
__device__ unsigned g_wqkvT[(size_t)1024 * 3072]; // paired B-frag (gemm1 B)
__device__ unsigned g_woutT[(size_t)1024 * 1024]; // paired B-frag (gemm2 B)

__device__ __forceinline__ unsigned f2tf32(float x) {
    unsigned y;
    asm("cvt.rna.tf32.f32 %0, %1;" : "=r"(y) : "f"(x));
    return y;
}

__device__ __forceinline__ void mma_tf32(float* d, const unsigned* a, const unsigned* b) {
    asm volatile(
        "mma.sync.aligned.m16n8k8.row.col.f32.tf32.tf32.f32 "
        "{%0,%1,%2,%3}, {%4,%5,%6,%7}, {%8,%9}, {%0,%1,%2,%3};"
        : "+f"(d[0]), "+f"(d[1]), "+f"(d[2]), "+f"(d[3])
        : "r"(a[0]), "r"(a[1]), "r"(a[2]), "r"(a[3]), "r"(b[0]), "r"(b[1]));
}

__device__ __forceinline__ unsigned sptr(const void* p) {
    return (unsigned)__cvta_generic_to_shared(p);
}

__device__ __forceinline__ void cpa16(unsigned s, const void* g) {
    asm volatile("cp.async.cg.shared.global [%0], [%1], 16;\n" :: "r"(s), "l"(g));
}

// ---------------------------------------------------------------------------
// permA: fp32 [R,C] -> A-fragment tiles (round-8 proven, unchanged)
// ---------------------------------------------------------------------------
__global__ __launch_bounds__(256) void permA_tf32(
    const float4* __restrict__ src, unsigned* __restrict__ dst,
    int C, int total4)
{
    int idx = blockIdx.x * 256 + threadIdx.x;
    if (idx >= total4) return;
    const int C4 = C >> 2;
    const int r = idx / C4;
    const int k = (idx - r * C4) * 4;
    float4 v = src[idx];
    const int Ct = C >> 3;
    const int mt = r >> 4, rm = r & 15;
    const int gp = rm & 7, im = rm >> 3;
    const int kt = k >> 3, ik = (k & 7) >> 2;
    unsigned* tb = dst + ((size_t)mt * Ct + kt) * 128 + ik * 2 + im;
    tb[(gp * 4 + 0) * 4] = f2tf32(v.x);
    tb[(gp * 4 + 1) * 4] = f2tf32(v.y);
    tb[(gp * 4 + 2) * 4] = f2tf32(v.z);
    tb[(gp * 4 + 3) * 4] = f2tf32(v.w);
}

// ---------------------------------------------------------------------------
// permB: fp32 W[K,N] -> PAIRED B-frag tiles.
// Pair (kt, np) = 128 words at ((kt*(Nt/2))+np)*128;
// word for element (k = kt*8+tg+ik*4, n = np*16 + pp*8 + g):
//   (g*4+tg)*4 + pp*2 + ik
// ---------------------------------------------------------------------------
__global__ __launch_bounds__(256) void permB_tf32(
    const float4* __restrict__ src, unsigned* __restrict__ dst,
    int N, int total4)
{
    int idx = blockIdx.x * 256 + threadIdx.x;
    if (idx >= total4) return;
    const int N4 = N >> 2;
    const int k = idx / N4;
    const int n = (idx - k * N4) * 4;
    float4 v = src[idx];
    const int Np = N >> 4;                 // pairs per k-row
    const int kt = k >> 3, tg = k & 3, ik = (k & 7) >> 2;
    const int nt = n >> 3, g0 = n & 7;     // g0 in {0,4}; all 4 in same nt
    const int np = nt >> 1, pp = nt & 1;
    unsigned* tb = dst + ((size_t)kt * Np + np) * 128 + pp * 2 + ik;
    tb[((g0 + 0) * 4 + tg) * 4] = f2tf32(v.x);
    tb[((g0 + 1) * 4 + tg) * 4] = f2tf32(v.y);
    tb[((g0 + 2) * 4 + tg) * 4] = f2tf32(v.z);
    tb[((g0 + 3) * 4 + tg) * 4] = f2tf32(v.w);
}

// ---------------------------------------------------------------------------
// TF32 SGEMM (round-11 shape: 512 threads, 16 warps 4x4, 32x32 warp tile,
// 3-stage cp.async). B fragments now via paired LDS.128.
// mode 0: fp32 C + bias. mode 1: scatter to paired Q/K/V buffers.
// ---------------------------------------------------------------------------
#define STG_W 4096

__global__ __launch_bounds__(512, 2) void sgemm_tf32(
    const unsigned* __restrict__ A, const unsigned* __restrict__ B,
    const float* __restrict__ bias, void* __restrict__ Cout,
    unsigned* __restrict__ qbuf, unsigned* __restrict__ kbuf,
    unsigned* __restrict__ vbuf,
    int M, int N, int K, int mode)
{
    extern __shared__ unsigned smg[];
    unsigned* As = smg;                 // [3][4096]
    unsigned* Bs = smg + 3 * STG_W;     // [3][4096]

    const int tid = threadIdx.x;
    const int bx = blockIdx.x, by = blockIdx.y;
    const int lane = tid & 31, wid = tid >> 5;
    const int g = lane >> 2, tig = lane & 3;
    const int wm = (wid & 3) * 32;
    const int wn = (wid >> 2) * 32;
    const int Ct = K >> 3;

    const int amt = tid >> 6;
    const int aq  = (tid & 63) * 8;
    const int bkt = tid >> 7;
    const int bq  = (tid & 127) * 8;

    const unsigned* abase = A + ((size_t)(by * 8 + amt) * Ct) * 128 + aq;
    // paired B: k-row stride = (N/16)*128 = N*8 words; block at bx*8 pairs
    const unsigned* bbase = B + (size_t)bx * 1024 + bq;
    const size_t browstride = (size_t)N * 8;

    const unsigned sa_base = sptr(&As[amt * 512 + aq]);
    const unsigned sb_base = sptr(&Bs[bkt * 1024 + bq]);

    float acc[2][4][4];
#pragma unroll
    for (int mt = 0; mt < 2; mt++)
#pragma unroll
        for (int nt = 0; nt < 4; nt++)
#pragma unroll
            for (int i = 0; i < 4; i++) acc[mt][nt][i] = 0.0f;

    const int nt_iters = K >> 5;

#pragma unroll
    for (int p = 0; p < 2; p++) {
        const unsigned* ag = abase + p * 4 * 128;
        const unsigned* bg = bbase + (size_t)(p * 4 + bkt) * browstride;
        const unsigned sa = sa_base + p * (STG_W * 4);
        const unsigned sb = sb_base + p * (STG_W * 4);
#pragma unroll
        for (int i = 0; i < 2; i++) cpa16(sa + i * 16, ag + i * 4);
#pragma unroll
        for (int i = 0; i < 2; i++) cpa16(sb + i * 16, bg + i * 4);
        asm volatile("cp.async.commit_group;\n");
    }

    for (int t = 0; t < nt_iters; t++) {
        if (t + 1 < nt_iters)
            asm volatile("cp.async.wait_group 1;\n");
        else
            asm volatile("cp.async.wait_group 0;\n");
        __syncthreads();

        if (t + 2 < nt_iters) {
            const int s = (t + 2) % 3;
            const unsigned* ag = abase + (t + 2) * 4 * 128;
            const unsigned* bg = bbase + (size_t)((t + 2) * 4 + bkt) * browstride;
            const unsigned sa = sa_base + s * (STG_W * 4);
            const unsigned sb = sb_base + s * (STG_W * 4);
#pragma unroll
            for (int i = 0; i < 2; i++) cpa16(sa + i * 16, ag + i * 4);
#pragma unroll
            for (int i = 0; i < 2; i++) cpa16(sb + i * 16, bg + i * 4);
        }
        asm volatile("cp.async.commit_group;\n");

        const unsigned* Ab = As + (t % 3) * STG_W;
        const unsigned* Bb = Bs + (t % 3) * STG_W;

#pragma unroll
        for (int ks = 0; ks < 4; ks++) {
            uint4 af[2];
            uint4 bp[2];
#pragma unroll
            for (int mt = 0; mt < 2; mt++)
                af[mt] = *(const uint4*)&Ab[(((wid & 3) * 2 + mt) * 4 + ks) * 128 + lane * 4];
#pragma unroll
            for (int pl = 0; pl < 2; pl++)
                bp[pl] = *(const uint4*)&Bb[ks * 1024 + ((wid >> 2) * 2 + pl) * 128 + lane * 4];
#pragma unroll
            for (int mt = 0; mt < 2; mt++) {
#pragma unroll
                for (int pl = 0; pl < 2; pl++) {
                    mma_tf32(acc[mt][pl * 2 + 0], (const unsigned*)&af[mt],
                             (const unsigned*)&bp[pl].x);
                    mma_tf32(acc[mt][pl * 2 + 1], (const unsigned*)&af[mt],
                             (const unsigned*)&bp[pl].z);
                }
            }
        }
    }

    if (mode == 1) {
#pragma unroll
        for (int mt = 0; mt < 2; mt++) {
            const int row = by * 128 + wm + mt * 16 + g;
            const int bb = row >> 11;
            const int s = row & 2047;
#pragma unroll
            for (int nt = 0; nt < 4; nt++) {
                const int col = bx * 128 + wn + nt * 8 + 2 * tig;
                unsigned v00 = f2tf32(acc[mt][nt][0]);
                unsigned v01 = f2tf32(acc[mt][nt][1]);
                unsigned v10 = f2tf32(acc[mt][nt][2]);
                unsigned v11 = f2tf32(acc[mt][nt][3]);
                if (col < 1024) {            // Q -> A-frag (unchanged layout)
                    const int h = col >> 6, d = col & 63;
                    const int bh = bb * 16 + h;
                    size_t base = (((size_t)(bh * 16 + (s >> 7)) * 8 + ((s & 127) >> 4)) * 8
                                   + (d >> 3)) * 128;
                    const int gq = s & 7;
                    const int w0 = (gq * 4 + (d & 3)) * 4 + ((d & 7) >> 2) * 2;
                    const int d1 = d + 1;
                    const int w1 = (gq * 4 + (d1 & 3)) * 4 + ((d1 & 7) >> 2) * 2;
                    uint2 u0; u0.x = v00; u0.y = v10;
                    uint2 u1; u1.x = v01; u1.y = v11;
                    *(uint2*)&qbuf[base + w0] = u0;
                    *(uint2*)&qbuf[base + w1] = u1;
                } else if (col < 2048) {     // K -> PAIRED B-frag (n=key,k=dim)
                    const int h = (col - 1024) >> 6, d = (col - 1024) & 63;
                    const int bh = bb * 16 + h;
                    const int tt = s >> 6, key = s & 63;
                    unsigned* blk = kbuf + ((size_t)(bh * 32 + tt)) * 4096;
                    const int gk = key & 7;
                    const int ik = (d & 7) >> 2;           // same for d, d+1
                    const int ntk0 = key >> 3, ntk1 = (key + 8) >> 3;
                    const int tp0 = (d >> 3) * 4 + (ntk0 >> 1);
                    const int tp1 = (d >> 3) * 4 + (ntk1 >> 1);
                    const int pp0 = ntk0 & 1, pp1 = ntk1 & 1;
                    const int ln0 = gk * 4 + (d & 3);
                    const int ln1 = gk * 4 + ((d + 1) & 3);
                    blk[tp0 * 128 + ln0 * 4 + pp0 * 2 + ik] = v00;
                    blk[tp0 * 128 + ln1 * 4 + pp0 * 2 + ik] = v01;
                    blk[tp1 * 128 + ln0 * 4 + pp1 * 2 + ik] = v10;
                    blk[tp1 * 128 + ln1 * 4 + pp1 * 2 + ik] = v11;
                } else {                     // V -> PAIRED B-frag (n=dim,k=key)
                    const int h = (col - 2048) >> 6, d = (col - 2048) & 63;
                    const int bh = bb * 16 + h;
                    const int tt = s >> 6, key = s & 63;
                    unsigned* blk = vbuf + ((size_t)(bh * 32 + tt)) * 4096;
                    const int tigv = key & 3, ikv = (key & 7) >> 2;
                    const int ntd = d >> 3;                // same for d, d+1
                    const int np = ntd >> 1, pp = ntd & 1;
                    const int ks0 = key >> 3, ks1 = (key + 8) >> 3;
                    const int ln0 = (d & 7) * 4 + tigv;
                    const int ln1 = ((d + 1) & 7) * 4 + tigv;
                    blk[(ks0 * 4 + np) * 128 + ln0 * 4 + pp * 2 + ikv] = v00;
                    blk[(ks0 * 4 + np) * 128 + ln1 * 4 + pp * 2 + ikv] = v01;
                    blk[(ks1 * 4 + np) * 128 + ln0 * 4 + pp * 2 + ikv] = v10;
                    blk[(ks1 * 4 + np) * 128 + ln1 * 4 + pp * 2 + ikv] = v11;
                }
            }
        }
    } else {
        float* C = (float*)Cout;
        float bv0[4], bv1[4];
#pragma unroll
        for (int nt = 0; nt < 4; nt++) {
            int col = bx * 128 + wn + nt * 8 + 2 * tig;
            bv0[nt] = bias ? bias[col] : 0.0f;
            bv1[nt] = bias ? bias[col + 1] : 0.0f;
        }
#pragma unroll
        for (int mt = 0; mt < 2; mt++) {
            int row = by * 128 + wm + mt * 16 + g;
#pragma unroll
            for (int nt = 0; nt < 4; nt++) {
                int col = bx * 128 + wn + nt * 8 + 2 * tig;
                float2 s0, s1;
                s0.x = acc[mt][nt][0] + bv0[nt];
                s0.y = acc[mt][nt][1] + bv1[nt];
                s1.x = acc[mt][nt][2] + bv0[nt];
                s1.y = acc[mt][nt][3] + bv1[nt];
                *(float2*)(C + (size_t)row * N + col) = s0;
                *(float2*)(C + (size_t)(row + 8) * N + col) = s1;
            }
        }
    }
}

// ---------------------------------------------------------------------------
// Fragment-major flash attention (round-13 structure) with PAIRED K/V:
// each K/V fragment fetch is one LDS.128 serving two n-tiles.
// 128 -> 64 wide LDS per tile. Bit-identical math.
// ---------------------------------------------------------------------------
#define KVW 4096

__global__ __launch_bounds__(256, 2) void attn_tc(
    const unsigned* __restrict__ qbuf, const unsigned* __restrict__ kbuf,
    const unsigned* __restrict__ vbuf, const int* __restrict__ mask,
    unsigned* __restrict__ ctx)
{
    extern __shared__ unsigned sm[];
    unsigned* Ksm = sm;                       // [2][4096]
    unsigned* Vsm = sm + 2 * KVW;             // [2][4096]
    unsigned* Pw  = sm + 4 * KVW;             // [8 warps][1024]
    int*      Mk  = (int*)(sm + 4 * KVW + 8192);  // [2][64]

    const int tid = threadIdx.x;
    const int lane = tid & 31, wid = tid >> 5;
    const int g = lane >> 2, tig = lane & 3;

    const int qt = blockIdx.x;
    const int h  = blockIdx.y;
    const int b  = blockIdx.z;
    const int bh = b * 16 + h;

    const unsigned* qbase = qbuf + (((size_t)(bh * 16 + qt) * 8 + wid) * 8) * 128;
    uint4 qa[8];
#pragma unroll
    for (int ks = 0; ks < 8; ks++)
        qa[ks] = *(const uint4*)&qbase[ks * 128 + lane * 4];

    const int off = tid * 16;
    const unsigned sk_base = sptr(&Ksm[off]);
    const unsigned sv_base = sptr(&Vsm[off]);
    const unsigned* kblk0 = kbuf + ((size_t)bh * 32) * KVW;
    const unsigned* vblk0 = vbuf + ((size_t)bh * 32) * KVW;

    {
#pragma unroll
        for (int i = 0; i < 4; i++) cpa16(sk_base + i * 16, kblk0 + off + i * 4);
#pragma unroll
        for (int i = 0; i < 4; i++) cpa16(sv_base + i * 16, vblk0 + off + i * 4);
        if (tid < 16) cpa16(sptr(&Mk[tid * 4]), mask + b * 2048 + tid * 4);
        asm volatile("cp.async.commit_group;\n");
    }

    float O[8][4];
#pragma unroll
    for (int nt = 0; nt < 8; nt++)
#pragma unroll
        for (int i = 0; i < 4; i++) O[nt][i] = 0.0f;
    float mA = -1e30f, mB = -1e30f, lA = 0.0f, lB = 0.0f;

    unsigned* Pme = Pw + wid * 1024;

    for (int t = 0; t < 32; t++) {
        asm volatile("cp.async.wait_group 0;\n");
        __syncthreads();

        if (t + 1 < 32) {
            const int s = (t + 1) & 1;
            const unsigned* kg = kblk0 + (size_t)(t + 1) * KVW + off;
            const unsigned* vg = vblk0 + (size_t)(t + 1) * KVW + off;
            const unsigned sk = sk_base + s * (KVW * 4);
            const unsigned sv = sv_base + s * (KVW * 4);
#pragma unroll
            for (int i = 0; i < 4; i++) cpa16(sk + i * 16, kg + i * 4);
#pragma unroll
            for (int i = 0; i < 4; i++) cpa16(sv + i * 16, vg + i * 4);
            if (tid < 16) cpa16(sptr(&Mk[s * 64 + tid * 4]),
                                mask + b * 2048 + (t + 1) * 64 + tid * 4);
            asm volatile("cp.async.commit_group;\n");
        }

        const unsigned* Kb = Ksm + (t & 1) * KVW;
        const unsigned* Vb = Vsm + (t & 1) * KVW;
        const int*      Mb = Mk + (t & 1) * 64;

        // ---- S = Q K^T : paired LDS.128 (one load -> two nt fragments) ----
        float s[8][4];
#pragma unroll
        for (int nt = 0; nt < 8; nt++)
#pragma unroll
            for (int i = 0; i < 4; i++) s[nt][i] = 0.0f;

#pragma unroll
        for (int ks = 0; ks < 8; ks++) {
#pragma unroll
            for (int np = 0; np < 4; np++) {
                uint4 bp = *(const uint4*)&Kb[(ks * 4 + np) * 128 + lane * 4];
                mma_tf32(s[np * 2 + 0], (const unsigned*)&qa[ks], (const unsigned*)&bp.x);
                mma_tf32(s[np * 2 + 1], (const unsigned*)&qa[ks], (const unsigned*)&bp.z);
            }
        }

        // ---- mask + online softmax ----
        float mxA = -1e30f, mxB = -1e30f;
#pragma unroll
        for (int nt = 0; nt < 8; nt++) {
            const int c = nt * 8 + 2 * tig;
            const int m0 = Mb[c], m1 = Mb[c + 1];
            s[nt][0] = (m0 == 0) ? NEGV : s[nt][0] * 0.125f;
            s[nt][1] = (m1 == 0) ? NEGV : s[nt][1] * 0.125f;
            s[nt][2] = (m0 == 0) ? NEGV : s[nt][2] * 0.125f;
            s[nt][3] = (m1 == 0) ? NEGV : s[nt][3] * 0.125f;
            mxA = fmaxf(mxA, fmaxf(s[nt][0], s[nt][1]));
            mxB = fmaxf(mxB, fmaxf(s[nt][2], s[nt][3]));
        }
        mxA = fmaxf(mxA, __shfl_xor_sync(0xffffffffu, mxA, 1));
        mxA = fmaxf(mxA, __shfl_xor_sync(0xffffffffu, mxA, 2));
        mxB = fmaxf(mxB, __shfl_xor_sync(0xffffffffu, mxB, 1));
        mxB = fmaxf(mxB, __shfl_xor_sync(0xffffffffu, mxB, 2));

        const float mnA = fmaxf(mA, mxA);
        const float mnB = fmaxf(mB, mxB);
        const float alphaA = __expf(mA - mnA);
        const float alphaB = __expf(mB - mnB);
        float sumA = 0.0f, sumB = 0.0f;
#pragma unroll
        for (int nt = 0; nt < 8; nt++) {
            s[nt][0] = __expf(s[nt][0] - mnA);
            s[nt][1] = __expf(s[nt][1] - mnA);
            s[nt][2] = __expf(s[nt][2] - mnB);
            s[nt][3] = __expf(s[nt][3] - mnB);
            sumA += s[nt][0] + s[nt][1];
            sumB += s[nt][2] + s[nt][3];
        }
        sumA += __shfl_xor_sync(0xffffffffu, sumA, 1);
        sumA += __shfl_xor_sync(0xffffffffu, sumA, 2);
        sumB += __shfl_xor_sync(0xffffffffu, sumB, 1);
        sumB += __shfl_xor_sync(0xffffffffu, sumB, 2);
        lA = lA * alphaA + sumA;  mA = mnA;
        lB = lB * alphaB + sumB;  mB = mnB;
#pragma unroll
        for (int nt = 0; nt < 8; nt++) {
            O[nt][0] *= alphaA; O[nt][1] *= alphaA;
            O[nt][2] *= alphaB; O[nt][3] *= alphaB;
        }

        // ---- P -> per-warp A-frag smem (all 8 k-tiles), one syncwarp ----
#pragma unroll
        for (int nt = 0; nt < 8; nt++) {
            const int d0 = 2 * tig, d1 = 2 * tig + 1;
            const int w0 = (g * 4 + (d0 & 3)) * 4 + ((d0 & 7) >> 2) * 2;
            const int w1 = (g * 4 + (d1 & 3)) * 4 + ((d1 & 7) >> 2) * 2;
            uint2 u0; u0.x = f2tf32(s[nt][0]); u0.y = f2tf32(s[nt][2]);
            uint2 u1; u1.x = f2tf32(s[nt][1]); u1.y = f2tf32(s[nt][3]);
            *(uint2*)&Pme[nt * 128 + w0] = u0;
            *(uint2*)&Pme[nt * 128 + w1] = u1;
        }
        __syncwarp();

        // ---- O += P V : paired LDS.128 for V ----
#pragma unroll
        for (int ks = 0; ks < 8; ks++) {
            const uint4 pa = *(const uint4*)&Pme[ks * 128 + lane * 4];
#pragma unroll
            for (int np = 0; np < 4; np++) {
                uint4 bp = *(const uint4*)&Vb[(ks * 4 + np) * 128 + lane * 4];
                mma_tf32(O[np * 2 + 0], (const unsigned*)&pa, (const unsigned*)&bp.x);
                mma_tf32(O[np * 2 + 1], (const unsigned*)&pa, (const unsigned*)&bp.z);
            }
        }
    }

    // epilogue: ctx in A-frag tile layout (Ct = 128) for gemm2
    const float invA = 1.0f / lA;
    const float invB = 1.0f / lB;
    const int mt = (b * 2048 + qt * 128 + wid * 16) >> 4;
#pragma unroll
    for (int nt = 0; nt < 8; nt++) {
        const int kt = h * 8 + nt;
        unsigned* tb = ctx + ((size_t)mt * 128 + kt) * 128;
        const int tig2 = 2 * tig;
        const int ik = tig2 >> 2, tp = tig2 & 3;
        uint2 w0, w1;
        w0.x = f2tf32(O[nt][0] * invA);
        w0.y = f2tf32(O[nt][2] * invB);
        w1.x = f2tf32(O[nt][1] * invA);
        w1.y = f2tf32(O[nt][3] * invB);
        *(uint2*)&tb[(g * 4 + tp) * 4 + ik * 2]     = w0;
        *(uint2*)&tb[(g * 4 + tp + 1) * 4 + ik * 2] = w1;
    }
}

// ---------------------------------------------------------------------------
extern "C" void kernel_launch(void* const* d_in, const int* in_sizes, int n_in,
                              void* d_out, int out_size)
{
    const float* qs   = (const float*)d_in[0];
    const int*   mask = (const int*)d_in[1];
    const float* Wqkv = (const float*)d_in[2];
    const float* Wout = (const float*)d_in[3];
    const float* bout = (const float*)d_in[4];
    float* out = (float*)d_out;

    unsigned *qP, *kP, *vP, *ctxP, *qsT, *wqkvT, *woutT;
    cudaGetSymbolAddress((void**)&qP,    g_q);
    cudaGetSymbolAddress((void**)&kP,    g_k);
    cudaGetSymbolAddress((void**)&vP,    g_v);
    cudaGetSymbolAddress((void**)&ctxP,  g_ctx);
    cudaGetSymbolAddress((void**)&qsT,   g_qsT);
    cudaGetSymbolAddress((void**)&wqkvT, g_wqkvT);
    cudaGetSymbolAddress((void**)&woutT, g_woutT);

    const int gemmSmem = 6 * STG_W * 4;  // 98304 B
    cudaFuncSetAttribute(sgemm_tf32,
                         cudaFuncAttributeMaxDynamicSharedMemorySize, gemmSmem);

    const int attnSmem = (4 * KVW + 8192 + 128) * 4;  // 98816 B
    cudaFuncSetAttribute(attn_tc,
                         cudaFuncAttributeMaxDynamicSharedMemorySize, attnSmem);

    // 0) pre-convert + permute inputs (B operands now paired layout)
    permA_tf32<<<4096, 256>>>((const float4*)qs, qsT, 1024, 4096 * 1024 / 4);
    permB_tf32<<<3072, 256>>>((const float4*)Wqkv, wqkvT, 3072, 1024 * 3072 / 4);
    permB_tf32<<<1024, 256>>>((const float4*)Wout, woutT, 1024, 1024 * 1024 / 4);

    // 1) qkv = qs @ Wqkv, scattered into fragment-major Q/K/V buffers
    sgemm_tf32<<<dim3(24, 32), 512, gemmSmem>>>(
        qsT, wqkvT, nullptr, nullptr, qP, kP, vP, 4096, 3072, 1024, 1);

    // 2) fused masked attention -> ctx (A-frag layout)
    attn_tc<<<dim3(16, 16, 2), 256, attnSmem>>>(qP, kP, vP, mask, ctxP);

    // 3) out = ctx @ Wout + bout  (fp32 final)
    sgemm_tf32<<<dim3(8, 32), 512, gemmSmem>>>(
        ctxP, woutT, bout, out, nullptr, nullptr, nullptr, 4096, 1024, 1024, 0);
}